// round 12
// baseline (speedup 1.0000x reference)
#include <cuda_runtime.h>
#include <cuda_fp16.h>
#include <cstddef>
#include <cstdint>

#define B_TOTAL 32768
#define T_SEQ   7
#define D_IN    40
#define H_DIM   64
#define FC_DIM  32
#define ROWS    128
#define BLKT    1024
#define NBLK    (B_TOTAL / ROWS)   // 256
#define AST     136                // padded stride in halfs (272 B)

// ---------------- smem byte offsets ----------------
#define SM_A0H  0                       // A buf0 hi [128][AST] halfs
#define SM_A1H  34816                   // A buf1 hi
#define SM_BH   69632                   // W hi  [256][AST] halfs
#define SM_BL   139264                  // W lo
#define SM_BIAS 208896                  // 256 fp32
#define SM_FC   209920                  // FC weights fp32
#define SM_TOTAL 218372

// phase-A hidden states fp32: [blk][t][128][64]
__device__ __align__(16) float g_scr[(size_t)NBLK * T_SEQ * ROWS * H_DIM];

// ---------------- helpers ----------------
__device__ __forceinline__ uint32_t smem_u32(const void* p) {
    uint32_t a;
    asm("{ .reg .u64 t; cvta.to.shared.u64 t, %1; cvt.u32.u64 %0, t; }" : "=r"(a) : "l"(p));
    return a;
}
__device__ __forceinline__ void ldsm4(uint32_t r[4], uint32_t addr) {
    asm volatile("ldmatrix.sync.aligned.m8n8.x4.shared.b16 {%0,%1,%2,%3}, [%4];"
        : "=r"(r[0]), "=r"(r[1]), "=r"(r[2]), "=r"(r[3]) : "r"(addr));
}
__device__ __forceinline__ void mma16816(float* c, const uint32_t a[4],
                                         uint32_t b0, uint32_t b1) {
    asm volatile(
        "mma.sync.aligned.m16n8k16.row.col.f32.f16.f16.f32 "
        "{%0,%1,%2,%3}, {%4,%5,%6,%7}, {%8,%9}, {%0,%1,%2,%3};"
        : "+f"(c[0]), "+f"(c[1]), "+f"(c[2]), "+f"(c[3])
        : "r"(a[0]), "r"(a[1]), "r"(a[2]), "r"(a[3]), "r"(b0), "r"(b1));
}
__device__ __forceinline__ float sigf(float x) {
    return __fdividef(1.0f, 1.0f + __expf(-x));
}
__device__ __forceinline__ float tanhf_fast(float x) {
    return __fdividef(2.0f, 1.0f + __expf(-2.0f * x)) - 1.0f;
}
__device__ __forceinline__ void split16(float v, __half& h, __half& l) {
    h = __float2half_rn(v);
    l = __float2half_rn(v - __half2float(h));
}

// ---------------- weight staging: fp32 -> split fp16 [256][AST] ----------------
// cols [0,Kx) = W_in, cols [64,128) = W_hh (combined A-tile K layout)
__device__ void stage_weights(const float* __restrict__ Wx, int Kx,
                              const float* __restrict__ Wh,
                              const float* __restrict__ bi, const float* __restrict__ bh,
                              unsigned char* sm, int tid)
{
    uint4 z = make_uint4(0, 0, 0, 0);
    uint4* zb = (uint4*)(sm + SM_BH);
    for (int i = tid; i < (2 * 69632) / 16; i += BLKT) zb[i] = z;
    __syncthreads();

    for (int e = tid; e < 256 * Kx; e += BLKT) {
        int c = e / Kx, k = e % Kx;
        __half h, l; split16(Wx[e], h, l);
        uint32_t off = (uint32_t)(c * AST + k) * 2;
        *(__half*)(sm + SM_BH + off) = h;
        *(__half*)(sm + SM_BL + off) = l;
    }
    for (int e = tid; e < 256 * H_DIM; e += BLKT) {
        int c = e / H_DIM, k = e % H_DIM;
        __half h, l; split16(Wh[e], h, l);
        uint32_t off = (uint32_t)(c * AST + 64 + k) * 2;
        *(__half*)(sm + SM_BH + off) = h;
        *(__half*)(sm + SM_BL + off) = l;
    }
    float* sB = (float*)(sm + SM_BIAS);
    for (int i = tid; i < 256; i += BLKT) sB[i] = bi[i] + bh[i];
}

// ---------------- one LSTM layer (7 steps), 1 sync/step, prefetched staging ---
template <bool PA>
__device__ void run_phase(unsigned char* sm, uint32_t smb,
                          const float* __restrict__ x, int b0, int blk, int tid)
{
    const int w = tid >> 5, lane = tid & 31;
    const int m0 = (w >> 2) * 16, j0 = (w & 3) * 16;   // 8 m-tiles x 4 n-tiles
    const int tig = lane & 3, g8 = lane >> 2;
    const int part = lane >> 3, l = lane & 7;

    const uint32_t aoff =
        (uint32_t)(((m0 + (part & 1) * 8 + l) * AST + (part >> 1) * 8) * 2);
    const uint32_t boff =
        (uint32_t)(((j0 + (part >> 1) * 8 + l) * AST + (part & 1) * 8) * 2);
    const uint32_t aBh = smb + SM_BH + boff;
    const uint32_t aBl = smb + SM_BL + boff;
    const uint32_t aAbuf[2] = { smb + SM_A0H + aoff, smb + SM_A1H + aoff };
    const float* sBias = (const float*)(sm + SM_BIAS);

    float c[8];
#pragma unroll
    for (int i = 0; i < 8; i++) c[i] = 0.0f;

    // ---- pre-stage t=0 into buf0 ----
    if (PA) {
#pragma unroll
        for (int i = 0; i < 3; i++) {
            int fi = tid + i * BLKT;            // 0..2559 float2 of x_0
            if (fi < 2560) {
                int row = fi / 20, p = fi % 20;
                float2 v = *(const float2*)(
                    x + ((size_t)(b0 + row) * T_SEQ + 0) * D_IN + 2 * p);
                *(__half2*)(sm + SM_A0H + (uint32_t)((row * AST + 2 * p) * 2)) =
                    __halves2half2(__float2half_rn(v.x), __float2half_rn(v.y));
            }
        }
    } else {
        const float2* src = (const float2*)(g_scr + (size_t)blk * T_SEQ * (ROWS * H_DIM));
#pragma unroll
        for (int i = 0; i < 4; i++) {
            int fi = tid + i * BLKT;            // 0..4095
            int row = fi >> 5, jp = fi & 31;
            float2 v = src[fi];
            *(__half2*)(sm + SM_A0H + (uint32_t)((row * AST + 2 * jp) * 2)) =
                __halves2half2(__float2half_rn(v.x), __float2half_rn(v.y));
        }
    }

    for (int t = 0; t < T_SEQ; t++) {
        __syncthreads();   // read-buffer (x_t staged + h_{t-1} from epi) ready

        // ---- prefetch t+1 staging loads into registers (off critical path) ----
        float2 pf[4];
        if (PA) {
            if (t + 1 < T_SEQ) {
#pragma unroll
                for (int i = 0; i < 3; i++) {
                    int fi = tid + i * BLKT;
                    if (fi < 2560) {
                        int row = fi / 20, p = fi % 20;
                        pf[i] = *(const float2*)(
                            x + ((size_t)(b0 + row) * T_SEQ + (t + 1)) * D_IN + 2 * p);
                    }
                }
            }
        } else {
            if (t + 1 < T_SEQ) {
                const float2* src = (const float2*)(
                    g_scr + ((size_t)blk * T_SEQ + (t + 1)) * (ROWS * H_DIM));
#pragma unroll
                for (int i = 0; i < 4; i++) pf[i] = src[tid + i * BLKT];
            }
        }

        // ---- 2-term GEMM: acc = Ah@Bh + Ah@Bl ----
        const uint32_t aAh = aAbuf[t & 1];
        float acc[32];
#pragma unroll
        for (int i = 0; i < 32; i++) acc[i] = 0.0f;
#pragma unroll
        for (int ks = 0; ks < 8; ks++) {
            if (PA && ks == 3) continue;       // cols 48..63 are zero pad
            const uint32_t kb = (uint32_t)ks * 32;   // 16 halfs = 32 B
            uint32_t ah[4];
            ldsm4(ah, aAh + kb);
#pragma unroll
            for (int g4 = 0; g4 < 4; g4++) {
                uint32_t bh[4], bl[4];
                ldsm4(bh, aBh + (uint32_t)g4 * 64 * AST * 2 + kb);
                ldsm4(bl, aBl + (uint32_t)g4 * 64 * AST * 2 + kb);
                float* a0 = &acc[(g4 * 2 + 0) * 4];
                float* a1 = &acc[(g4 * 2 + 1) * 4];
                mma16816(a0, ah, bh[0], bh[1]);
                mma16816(a1, ah, bh[2], bh[3]);
                mma16816(a0, ah, bl[0], bl[1]);
                mma16816(a1, ah, bl[2], bl[3]);
            }
        }

        // ---- epilogue: gates -> c, h_t -> write buffer ----
        unsigned char* bufW = sm + ((t & 1) ? SM_A0H : SM_A1H);
        const bool last = (!PA) && (t == T_SEQ - 1);
        float* gscr = PA ? g_scr + ((size_t)blk * T_SEQ + t) * (ROWS * H_DIM) : nullptr;
#pragma unroll
        for (int rr = 0; rr < 2; rr++)
#pragma unroll
        for (int nt = 0; nt < 2; nt++) {
            const int jj = j0 + nt * 8 + 2 * tig;
            float2 bi = *(const float2*)(sBias + jj);
            float2 bf = *(const float2*)(sBias + 64 + jj);
            float2 bg = *(const float2*)(sBias + 128 + jj);
            float2 bo = *(const float2*)(sBias + 192 + jj);
            float hv[2];
#pragma unroll
            for (int e = 0; e < 2; e++) {
                float pi = acc[(0 * 2 + nt) * 4 + rr * 2 + e] + (e ? bi.y : bi.x);
                float pf_ = acc[(1 * 2 + nt) * 4 + rr * 2 + e] + (e ? bf.y : bf.x);
                float pg = acc[(2 * 2 + nt) * 4 + rr * 2 + e] + (e ? bg.y : bg.x);
                float po = acc[(3 * 2 + nt) * 4 + rr * 2 + e] + (e ? bo.y : bo.x);
                float ig = sigf(pi), fg = sigf(pf_);
                float gg = tanhf_fast(pg), og = sigf(po);
                int ci = (rr * 2 + nt) * 2 + e;
                float cn = fmaf(fg, c[ci], ig * gg);
                c[ci] = cn;
                hv[e] = og * tanhf_fast(cn);
            }
            const int row = m0 + rr * 8 + g8;
            if (last) {
                *(float2*)((float*)(sm + SM_A1H) + row * 64 + jj) =
                    make_float2(hv[0], hv[1]);
            } else {
                uint32_t off = (uint32_t)((row * AST + 64 + jj) * 2);
                *(__half2*)(bufW + off) =
                    __halves2half2(__float2half_rn(hv[0]), __float2half_rn(hv[1]));
                if (PA)
                    *(float2*)(gscr + row * 64 + jj) = make_float2(hv[0], hv[1]);
            }
        }

        // ---- store prefetched t+1 staging into the write buffer ----
        if (t + 1 < T_SEQ) {
            if (PA) {
#pragma unroll
                for (int i = 0; i < 3; i++) {
                    int fi = tid + i * BLKT;
                    if (fi < 2560) {
                        int row = fi / 20, p = fi % 20;
                        *(__half2*)(bufW + (uint32_t)((row * AST + 2 * p) * 2)) =
                            __halves2half2(__float2half_rn(pf[i].x),
                                           __float2half_rn(pf[i].y));
                    }
                }
            } else {
#pragma unroll
                for (int i = 0; i < 4; i++) {
                    int fi = tid + i * BLKT;
                    int row = fi >> 5, jp = fi & 31;
                    *(__half2*)(bufW + (uint32_t)((row * AST + 2 * jp) * 2)) =
                        __halves2half2(__float2half_rn(pf[i].x),
                                       __float2half_rn(pf[i].y));
                }
            }
        }
    }
}

__global__ void __launch_bounds__(BLKT, 1)
rainfall_lstm_hmma4_kernel(
    const float* __restrict__ x,
    const float* __restrict__ Wih0, const float* __restrict__ Whh0,
    const float* __restrict__ bih0, const float* __restrict__ bhh0,
    const float* __restrict__ Wih1, const float* __restrict__ Whh1,
    const float* __restrict__ bih1, const float* __restrict__ bhh1,
    const float* __restrict__ W1, const float* __restrict__ b1,
    const float* __restrict__ W2, const float* __restrict__ b2,
    float* __restrict__ out)
{
    extern __shared__ unsigned char sm[];
    const uint32_t smb = smem_u32(sm);
    const int tid = threadIdx.x;
    const int blk = blockIdx.x;
    const int b0 = blk * ROWS;

    // ---- phase A setup ----
    stage_weights(Wih0, D_IN, Whh0, bih0, bhh0, sm, tid);
    {   // zero both A buffers (x pad cols 40..63 stay 0 forever; h0 = 0)
        uint4 z = make_uint4(0, 0, 0, 0);
        uint4* za = (uint4*)(sm + SM_A0H);
        for (int i = tid; i < (2 * 34816) / 16; i += BLKT) za[i] = z;
    }
    __syncthreads();
    run_phase<true>(sm, smb, x, b0, blk, tid);
    __syncthreads();   // phase-A writes done before W restage

    // ---- phase B setup ----
    stage_weights(Wih1, H_DIM, Whh1, bih1, bhh1, sm, tid);
    {   // zero both A buffers (h0 = 0 for layer 1)
        uint4 z = make_uint4(0, 0, 0, 0);
        uint4* za = (uint4*)(sm + SM_A0H);
        for (int i = tid; i < (2 * 34816) / 16; i += BLKT) za[i] = z;
    }
    {   // FC weights
        float* fw = (float*)(sm + SM_FC);
        for (int i = tid; i < FC_DIM * H_DIM; i += BLKT) fw[i] = W1[i];
        if (tid < FC_DIM) { fw[2048 + tid] = b1[tid]; fw[2080 + tid] = W2[tid]; }
        if (tid == 0) fw[2112] = b2[0];
    }
    __syncthreads();
    run_phase<false>(sm, smb, nullptr, b0, blk, tid);
    __syncthreads();   // final fp32 h2 (in SM_A1H) complete

    // ---- FC head: one thread per row ----
    if (tid < ROWS) {
        const float* sFC = (const float*)(sm + SM_A1H);
        const float* fw = (const float*)(sm + SM_FC);
        float hv[H_DIM];
#pragma unroll
        for (int j = 0; j < H_DIM; j++) hv[j] = sFC[tid * 64 + j];
        float o = fw[2112];
#pragma unroll
        for (int r = 0; r < FC_DIM; r++) {
            float a = fw[2048 + r];
            const float* wr = fw + r * H_DIM;
#pragma unroll
            for (int j = 0; j < H_DIM; j++) a = fmaf(hv[j], wr[j], a);
            o = fmaf(fmaxf(a, 0.0f), fw[2080 + r], o);
        }
        out[b0 + tid] = o;
    }
}

extern "C" void kernel_launch(void* const* d_in, const int* in_sizes, int n_in,
                              void* d_out, int out_size)
{
    (void)in_sizes; (void)n_in; (void)out_size;
    const float* x    = (const float*)d_in[0];
    const float* Wih0 = (const float*)d_in[1];
    const float* Whh0 = (const float*)d_in[2];
    const float* bih0 = (const float*)d_in[3];
    const float* bhh0 = (const float*)d_in[4];
    const float* Wih1 = (const float*)d_in[5];
    const float* Whh1 = (const float*)d_in[6];
    const float* bih1 = (const float*)d_in[7];
    const float* bhh1 = (const float*)d_in[8];
    const float* W1   = (const float*)d_in[9];
    const float* b1   = (const float*)d_in[10];
    const float* W2   = (const float*)d_in[11];
    const float* b2   = (const float*)d_in[12];
    float* out = (float*)d_out;

    cudaFuncSetAttribute(rainfall_lstm_hmma4_kernel,
                         cudaFuncAttributeMaxDynamicSharedMemorySize,
                         SM_TOTAL);

    rainfall_lstm_hmma4_kernel<<<NBLK, BLKT, SM_TOTAL>>>(
        x, Wih0, Whh0, bih0, bhh0, Wih1, Whh1, bih1, bhh1,
        W1, b1, W2, b2, out);
}

// round 13
// speedup vs baseline: 1.5001x; 1.5001x over previous
#include <cuda_runtime.h>
#include <cuda_fp16.h>
#include <cstddef>
#include <cstdint>

#define B_TOTAL 32768
#define T_SEQ   7
#define D_IN    40
#define H_DIM   64
#define FC_DIM  32
#define ROWS    128
#define BLKT    512
#define NBLK    (B_TOTAL / ROWS)   // 256
#define AST     136                // padded stride in halfs (272 B)

// ---------------- smem byte offsets ----------------
#define SM_A0H  0                       // A buf0 hi [128][AST] halfs
#define SM_A1H  34816                   // A buf1 hi
#define SM_BH   69632                   // W hi  [256][AST] halfs
#define SM_BL   139264                  // W lo
#define SM_BIAS 208896                  // 256 fp32
#define SM_FC   209920                  // FC weights fp32
#define SM_TOTAL 218372

// phase-A hidden states, fp16: [blk][t][128][64]
__device__ __align__(16) __half g_scr16[(size_t)NBLK * T_SEQ * ROWS * H_DIM];

// ---------------- helpers ----------------
__device__ __forceinline__ uint32_t smem_u32(const void* p) {
    uint32_t a;
    asm("{ .reg .u64 t; cvta.to.shared.u64 t, %1; cvt.u32.u64 %0, t; }" : "=r"(a) : "l"(p));
    return a;
}
__device__ __forceinline__ void ldsm4(uint32_t r[4], uint32_t addr) {
    asm volatile("ldmatrix.sync.aligned.m8n8.x4.shared.b16 {%0,%1,%2,%3}, [%4];"
        : "=r"(r[0]), "=r"(r[1]), "=r"(r[2]), "=r"(r[3]) : "r"(addr));
}
__device__ __forceinline__ void mma16816(float* c, const uint32_t a[4],
                                         uint32_t b0, uint32_t b1) {
    asm volatile(
        "mma.sync.aligned.m16n8k16.row.col.f32.f16.f16.f32 "
        "{%0,%1,%2,%3}, {%4,%5,%6,%7}, {%8,%9}, {%0,%1,%2,%3};"
        : "+f"(c[0]), "+f"(c[1]), "+f"(c[2]), "+f"(c[3])
        : "r"(a[0]), "r"(a[1]), "r"(a[2]), "r"(a[3]), "r"(b0), "r"(b1));
}
__device__ __forceinline__ float tanh_ap(float x) {
    float y; asm("tanh.approx.f32 %0, %1;" : "=f"(y) : "f"(x)); return y;
}
__device__ __forceinline__ float sig_ap(float x) {
    return fmaf(0.5f, tanh_ap(0.5f * x), 0.5f);
}
__device__ __forceinline__ void split16(float v, __half& h, __half& l) {
    h = __float2half_rn(v);
    l = __float2half_rn(v - __half2float(h));
}

// ---------------- weight staging: fp32 -> split fp16 [256][AST] ----------------
// cols [0,Kx) = W_in, cols [64,128) = W_hh (combined A-tile K layout)
__device__ void stage_weights(const float* __restrict__ Wx, int Kx,
                              const float* __restrict__ Wh,
                              const float* __restrict__ bi, const float* __restrict__ bh,
                              unsigned char* sm, int tid)
{
    uint4 z = make_uint4(0, 0, 0, 0);
    uint4* zb = (uint4*)(sm + SM_BH);
    for (int i = tid; i < (2 * 69632) / 16; i += BLKT) zb[i] = z;
    __syncthreads();

    for (int e = tid; e < 256 * Kx; e += BLKT) {
        int c = e / Kx, k = e % Kx;
        __half h, l; split16(Wx[e], h, l);
        uint32_t off = (uint32_t)(c * AST + k) * 2;
        *(__half*)(sm + SM_BH + off) = h;
        *(__half*)(sm + SM_BL + off) = l;
    }
    for (int e = tid; e < 256 * H_DIM; e += BLKT) {
        int c = e / H_DIM, k = e % H_DIM;
        __half h, l; split16(Wh[e], h, l);
        uint32_t off = (uint32_t)(c * AST + 64 + k) * 2;
        *(__half*)(sm + SM_BH + off) = h;
        *(__half*)(sm + SM_BL + off) = l;
    }
    float* sB = (float*)(sm + SM_BIAS);
    for (int i = tid; i < 256; i += BLKT) sB[i] = bi[i] + bh[i];
}

// ---------------- one LSTM layer (7 steps), 1 sync/step, prefetched staging ---
template <bool PA>
__device__ void run_phase(unsigned char* sm, uint32_t smb,
                          const float* __restrict__ x, int b0, int blk, int tid)
{
    const int w = tid >> 5, lane = tid & 31;
    const int m0 = (w >> 2) * 32, j0 = (w & 3) * 16;
    const int tig = lane & 3, g8 = lane >> 2;
    const int part = lane >> 3, l = lane & 7;

    const uint32_t aoff =
        (uint32_t)(((m0 + (part & 1) * 8 + l) * AST + (part >> 1) * 8) * 2);
    const uint32_t boff =
        (uint32_t)(((j0 + (part >> 1) * 8 + l) * AST + (part & 1) * 8) * 2);
    const uint32_t aBh = smb + SM_BH + boff;
    const uint32_t aBl = smb + SM_BL + boff;
    const uint32_t aAbuf[2] = { smb + SM_A0H + aoff, smb + SM_A1H + aoff };
    const float* sBias = (const float*)(sm + SM_BIAS);

    float c[16];
#pragma unroll
    for (int i = 0; i < 16; i++) c[i] = 0.0f;

    // ---- pre-stage t=0 into buf0 ----
    if (PA) {
#pragma unroll
        for (int i = 0; i < 5; i++) {
            int fi = tid + i * BLKT;            // 0..2559 float2 of x_0
            if (fi < 2560) {
                int row = fi / 20, p = fi % 20;
                float2 v = *(const float2*)(
                    x + ((size_t)(b0 + row) * T_SEQ + 0) * D_IN + 2 * p);
                *(__half2*)(sm + SM_A0H + (uint32_t)((row * AST + 2 * p) * 2)) =
                    __halves2half2(__float2half_rn(v.x), __float2half_rn(v.y));
            }
        }
    } else {
        const uint4* src = (const uint4*)(g_scr16 + (size_t)blk * T_SEQ * (ROWS * H_DIM));
#pragma unroll
        for (int i = 0; i < 2; i++) {
            int fi = tid + i * BLKT;            // 0..1023 uint4 (8 halfs each)
            int row = fi >> 3, seg = fi & 7;
            *(uint4*)(sm + SM_A0H + (uint32_t)(row * (AST * 2) + seg * 16)) = src[fi];
        }
    }

    for (int t = 0; t < T_SEQ; t++) {
        __syncthreads();   // read buffer (x_t staged + h_{t-1} from epi) ready

        // ---- prefetch t+1 staging loads (latency off critical path) ----
        float2 pfx[5];
        uint4  pfh[2];
        if (t + 1 < T_SEQ) {
            if (PA) {
#pragma unroll
                for (int i = 0; i < 5; i++) {
                    int fi = tid + i * BLKT;
                    if (fi < 2560) {
                        int row = fi / 20, p = fi % 20;
                        pfx[i] = *(const float2*)(
                            x + ((size_t)(b0 + row) * T_SEQ + (t + 1)) * D_IN + 2 * p);
                    }
                }
            } else {
                const uint4* src = (const uint4*)(
                    g_scr16 + ((size_t)blk * T_SEQ + (t + 1)) * (ROWS * H_DIM));
#pragma unroll
                for (int i = 0; i < 2; i++) pfh[i] = src[tid + i * BLKT];
            }
        }

        // ---- 2-term GEMM: acc = Ah@Bh + Ah@Bl ----
        const uint32_t aAh = aAbuf[t & 1];
        float acc[64];
#pragma unroll
        for (int i = 0; i < 64; i++) acc[i] = 0.0f;
#pragma unroll
        for (int ks = 0; ks < 8; ks++) {
            if (PA && ks == 3) continue;       // cols 48..63 are zero pad
            const uint32_t kb = (uint32_t)ks * 32;   // 16 halfs = 32 B
            uint32_t ah[2][4];
            ldsm4(ah[0], aAh + kb);
            ldsm4(ah[1], aAh + 16 * AST * 2 + kb);
#pragma unroll
            for (int g4 = 0; g4 < 4; g4++) {
                uint32_t bh[4], bl[4];
                ldsm4(bh, aBh + (uint32_t)g4 * 64 * AST * 2 + kb);
                ldsm4(bl, aBl + (uint32_t)g4 * 64 * AST * 2 + kb);
#pragma unroll
                for (int mt = 0; mt < 2; mt++) {
                    float* a0 = &acc[((g4 * 2 + 0) * 2 + mt) * 4];
                    float* a1 = &acc[((g4 * 2 + 1) * 2 + mt) * 4];
                    mma16816(a0, ah[mt], bh[0], bh[1]);
                    mma16816(a1, ah[mt], bh[2], bh[3]);
                    mma16816(a0, ah[mt], bl[0], bl[1]);
                    mma16816(a1, ah[mt], bl[2], bl[3]);
                }
            }
        }

        // ---- epilogue: gates -> c, h_t -> write buffer ----
        unsigned char* bufW = sm + ((t & 1) ? SM_A0H : SM_A1H);
        const bool last = (!PA) && (t == T_SEQ - 1);
        __half* gscr = PA ?
            g_scr16 + ((size_t)blk * T_SEQ + t) * (ROWS * H_DIM) : nullptr;
#pragma unroll
        for (int mt = 0; mt < 2; mt++)
#pragma unroll
        for (int rr = 0; rr < 2; rr++)
#pragma unroll
        for (int nt = 0; nt < 2; nt++) {
            const int jj = j0 + nt * 8 + 2 * tig;
            float2 bi = *(const float2*)(sBias + jj);
            float2 bf = *(const float2*)(sBias + 64 + jj);
            float2 bg = *(const float2*)(sBias + 128 + jj);
            float2 bo = *(const float2*)(sBias + 192 + jj);
            float hv[2];
#pragma unroll
            for (int e = 0; e < 2; e++) {
                float pi = acc[((0 * 2 + nt) * 2 + mt) * 4 + rr * 2 + e] + (e ? bi.y : bi.x);
                float pf = acc[((1 * 2 + nt) * 2 + mt) * 4 + rr * 2 + e] + (e ? bf.y : bf.x);
                float pg = acc[((2 * 2 + nt) * 2 + mt) * 4 + rr * 2 + e] + (e ? bg.y : bg.x);
                float po = acc[((3 * 2 + nt) * 2 + mt) * 4 + rr * 2 + e] + (e ? bo.y : bo.x);
                float ig = sig_ap(pi), fg = sig_ap(pf);
                float gg = tanh_ap(pg), og = sig_ap(po);
                int ci = ((mt * 2 + rr) * 2 + nt) * 2 + e;
                float cn = fmaf(fg, c[ci], ig * gg);
                c[ci] = cn;
                hv[e] = og * tanh_ap(cn);
            }
            const int row = m0 + mt * 16 + rr * 8 + g8;
            if (last) {
                *(float2*)((float*)(sm + SM_A1H) + row * 64 + jj) =
                    make_float2(hv[0], hv[1]);
            } else {
                __half2 hp = __halves2half2(__float2half_rn(hv[0]),
                                            __float2half_rn(hv[1]));
                uint32_t off = (uint32_t)((row * AST + 64 + jj) * 2);
                *(__half2*)(bufW + off) = hp;
                if (PA)
                    *(__half2*)(gscr + row * 64 + jj) = hp;
            }
        }

        // ---- store prefetched t+1 staging into the write buffer ----
        if (t + 1 < T_SEQ) {
            if (PA) {
#pragma unroll
                for (int i = 0; i < 5; i++) {
                    int fi = tid + i * BLKT;
                    if (fi < 2560) {
                        int row = fi / 20, p = fi % 20;
                        *(__half2*)(bufW + (uint32_t)((row * AST + 2 * p) * 2)) =
                            __halves2half2(__float2half_rn(pfx[i].x),
                                           __float2half_rn(pfx[i].y));
                    }
                }
            } else {
#pragma unroll
                for (int i = 0; i < 2; i++) {
                    int fi = tid + i * BLKT;
                    int row = fi >> 3, seg = fi & 7;
                    *(uint4*)(bufW + (uint32_t)(row * (AST * 2) + seg * 16)) = pfh[i];
                }
            }
        }
    }
}

__global__ void __launch_bounds__(BLKT, 1)
rainfall_lstm_hmma5_kernel(
    const float* __restrict__ x,
    const float* __restrict__ Wih0, const float* __restrict__ Whh0,
    const float* __restrict__ bih0, const float* __restrict__ bhh0,
    const float* __restrict__ Wih1, const float* __restrict__ Whh1,
    const float* __restrict__ bih1, const float* __restrict__ bhh1,
    const float* __restrict__ W1, const float* __restrict__ b1,
    const float* __restrict__ W2, const float* __restrict__ b2,
    float* __restrict__ out)
{
    extern __shared__ unsigned char sm[];
    const uint32_t smb = smem_u32(sm);
    const int tid = threadIdx.x;
    const int blk = blockIdx.x;
    const int b0 = blk * ROWS;

    // ---- phase A setup ----
    stage_weights(Wih0, D_IN, Whh0, bih0, bhh0, sm, tid);
    {   // zero both A buffers (x pad cols 40..63 stay 0 forever; h0 = 0)
        uint4 z = make_uint4(0, 0, 0, 0);
        uint4* za = (uint4*)(sm + SM_A0H);
        for (int i = tid; i < (2 * 34816) / 16; i += BLKT) za[i] = z;
    }
    __syncthreads();
    run_phase<true>(sm, smb, x, b0, blk, tid);
    __syncthreads();   // phase-A writes done before W restage

    // ---- phase B setup ----
    stage_weights(Wih1, H_DIM, Whh1, bih1, bhh1, sm, tid);
    {   // zero both A buffers (h0 = 0 for layer 1)
        uint4 z = make_uint4(0, 0, 0, 0);
        uint4* za = (uint4*)(sm + SM_A0H);
        for (int i = tid; i < (2 * 34816) / 16; i += BLKT) za[i] = z;
    }
    {   // FC weights
        float* fw = (float*)(sm + SM_FC);
        for (int i = tid; i < FC_DIM * H_DIM; i += BLKT) fw[i] = W1[i];
        if (tid < FC_DIM) { fw[2048 + tid] = b1[tid]; fw[2080 + tid] = W2[tid]; }
        if (tid == 0) fw[2112] = b2[0];
    }
    __syncthreads();
    run_phase<false>(sm, smb, nullptr, b0, blk, tid);
    __syncthreads();   // final fp32 h2 (in SM_A1H) complete

    // ---- FC head: one thread per row ----
    if (tid < ROWS) {
        const float* sFC = (const float*)(sm + SM_A1H);
        const float* fw = (const float*)(sm + SM_FC);
        float hv[H_DIM];
#pragma unroll
        for (int j = 0; j < H_DIM; j++) hv[j] = sFC[tid * 64 + j];
        float o = fw[2112];
#pragma unroll
        for (int r = 0; r < FC_DIM; r++) {
            float a = fw[2048 + r];
            const float* wr = fw + r * H_DIM;
#pragma unroll
            for (int j = 0; j < H_DIM; j++) a = fmaf(hv[j], wr[j], a);
            o = fmaf(fmaxf(a, 0.0f), fw[2080 + r], o);
        }
        out[b0 + tid] = o;
    }
}

extern "C" void kernel_launch(void* const* d_in, const int* in_sizes, int n_in,
                              void* d_out, int out_size)
{
    (void)in_sizes; (void)n_in; (void)out_size;
    const float* x    = (const float*)d_in[0];
    const float* Wih0 = (const float*)d_in[1];
    const float* Whh0 = (const float*)d_in[2];
    const float* bih0 = (const float*)d_in[3];
    const float* bhh0 = (const float*)d_in[4];
    const float* Wih1 = (const float*)d_in[5];
    const float* Whh1 = (const float*)d_in[6];
    const float* bih1 = (const float*)d_in[7];
    const float* bhh1 = (const float*)d_in[8];
    const float* W1   = (const float*)d_in[9];
    const float* b1   = (const float*)d_in[10];
    const float* W2   = (const float*)d_in[11];
    const float* b2   = (const float*)d_in[12];
    float* out = (float*)d_out;

    cudaFuncSetAttribute(rainfall_lstm_hmma5_kernel,
                         cudaFuncAttributeMaxDynamicSharedMemorySize,
                         SM_TOTAL);

    rainfall_lstm_hmma5_kernel<<<NBLK, BLKT, SM_TOTAL>>>(
        x, Wih0, Whh0, bih0, bhh0, Wih1, Whh1, bih1, bhh1,
        W1, b1, W2, b2, out);
}

// round 14
// speedup vs baseline: 2.1202x; 1.4134x over previous
#include <cuda_runtime.h>
#include <cuda_fp16.h>
#include <cstddef>
#include <cstdint>

#define B_TOTAL 32768
#define T_SEQ   7
#define D_IN    40
#define H_DIM   64
#define FC_DIM  32
#define ROWS    128
#define BLKT    512
#define NBLK    (B_TOTAL / ROWS)   // 256
#define AST     136                // padded stride in halfs (272 B)

// ---------------- smem byte offsets ----------------
#define SM_A0H  0                       // A buf0 [128][AST] halfs
#define SM_A1H  34816                   // A buf1
#define SM_BH   69632                   // W fp16 [256][AST] halfs
#define SM_BIAS 139264                  // 256 fp32
#define SM_FC   140288                  // FC weights fp32
#define SM_TOTAL 148740

// phase-A hidden states, fp16: [blk][t][128][64]
__device__ __align__(16) __half g_scr16[(size_t)NBLK * T_SEQ * ROWS * H_DIM];

// ---------------- helpers ----------------
__device__ __forceinline__ uint32_t smem_u32(const void* p) {
    uint32_t a;
    asm("{ .reg .u64 t; cvta.to.shared.u64 t, %1; cvt.u32.u64 %0, t; }" : "=r"(a) : "l"(p));
    return a;
}
__device__ __forceinline__ void ldsm4(uint32_t r[4], uint32_t addr) {
    asm volatile("ldmatrix.sync.aligned.m8n8.x4.shared.b16 {%0,%1,%2,%3}, [%4];"
        : "=r"(r[0]), "=r"(r[1]), "=r"(r[2]), "=r"(r[3]) : "r"(addr));
}
__device__ __forceinline__ void mma16816(float* c, const uint32_t a[4],
                                         uint32_t b0, uint32_t b1) {
    asm volatile(
        "mma.sync.aligned.m16n8k16.row.col.f32.f16.f16.f32 "
        "{%0,%1,%2,%3}, {%4,%5,%6,%7}, {%8,%9}, {%0,%1,%2,%3};"
        : "+f"(c[0]), "+f"(c[1]), "+f"(c[2]), "+f"(c[3])
        : "r"(a[0]), "r"(a[1]), "r"(a[2]), "r"(a[3]), "r"(b0), "r"(b1));
}
__device__ __forceinline__ float tanh_ap(float x) {
    float y; asm("tanh.approx.f32 %0, %1;" : "=f"(y) : "f"(x)); return y;
}
__device__ __forceinline__ float sig_ap(float x) {
    return fmaf(0.5f, tanh_ap(0.5f * x), 0.5f);
}

// ---------------- weight staging: fp32 -> fp16 [256][AST] ----------------
// cols [0,Kx) = W_in, cols [64,128) = W_hh (combined A-tile K layout)
__device__ void stage_weights(const float* __restrict__ Wx, int Kx,
                              const float* __restrict__ Wh,
                              const float* __restrict__ bi, const float* __restrict__ bh,
                              unsigned char* sm, int tid)
{
    uint4 z = make_uint4(0, 0, 0, 0);
    uint4* zb = (uint4*)(sm + SM_BH);
    for (int i = tid; i < 69632 / 16; i += BLKT) zb[i] = z;
    __syncthreads();

    for (int e = tid; e < 256 * Kx; e += BLKT) {
        int c = e / Kx, k = e % Kx;
        *(__half*)(sm + SM_BH + (uint32_t)(c * AST + k) * 2) = __float2half_rn(Wx[e]);
    }
    for (int e = tid; e < 256 * H_DIM; e += BLKT) {
        int c = e / H_DIM, k = e % H_DIM;
        *(__half*)(sm + SM_BH + (uint32_t)(c * AST + 64 + k) * 2) = __float2half_rn(Wh[e]);
    }
    float* sB = (float*)(sm + SM_BIAS);
    for (int i = tid; i < 256; i += BLKT) sB[i] = bi[i] + bh[i];
}

// ---------------- one LSTM layer (7 steps), 1 sync/step, prefetched staging ---
template <bool PA>
__device__ void run_phase(unsigned char* sm, uint32_t smb,
                          const float* __restrict__ x, int b0, int blk, int tid)
{
    const int w = tid >> 5, lane = tid & 31;
    const int m0 = (w >> 2) * 32, j0 = (w & 3) * 16;
    const int tig = lane & 3, g8 = lane >> 2;
    const int part = lane >> 3, l = lane & 7;

    const uint32_t aoff =
        (uint32_t)(((m0 + (part & 1) * 8 + l) * AST + (part >> 1) * 8) * 2);
    const uint32_t boff =
        (uint32_t)(((j0 + (part >> 1) * 8 + l) * AST + (part & 1) * 8) * 2);
    const uint32_t aBh = smb + SM_BH + boff;
    const uint32_t aAbuf[2] = { smb + SM_A0H + aoff, smb + SM_A1H + aoff };
    const float* sBias = (const float*)(sm + SM_BIAS);

    float c[16];
#pragma unroll
    for (int i = 0; i < 16; i++) c[i] = 0.0f;

    // ---- pre-stage t=0 into buf0 ----
    if (PA) {
#pragma unroll
        for (int i = 0; i < 5; i++) {
            int fi = tid + i * BLKT;            // 0..2559 float2 of x_0
            if (fi < 2560) {
                int row = fi / 20, p = fi % 20;
                float2 v = *(const float2*)(
                    x + ((size_t)(b0 + row) * T_SEQ + 0) * D_IN + 2 * p);
                *(__half2*)(sm + SM_A0H + (uint32_t)((row * AST + 2 * p) * 2)) =
                    __halves2half2(__float2half_rn(v.x), __float2half_rn(v.y));
            }
        }
    } else {
        const uint4* src = (const uint4*)(g_scr16 + (size_t)blk * T_SEQ * (ROWS * H_DIM));
#pragma unroll
        for (int i = 0; i < 2; i++) {
            int fi = tid + i * BLKT;            // 0..1023 uint4 (8 halfs each)
            int row = fi >> 3, seg = fi & 7;
            *(uint4*)(sm + SM_A0H + (uint32_t)(row * (AST * 2) + seg * 16)) = src[fi];
        }
    }

    for (int t = 0; t < T_SEQ; t++) {
        __syncthreads();   // read buffer (x_t staged + h_{t-1} from epi) ready

        // ---- prefetch t+1 staging loads (latency off critical path) ----
        float2 pfx[5];
        uint4  pfh[2];
        if (t + 1 < T_SEQ) {
            if (PA) {
#pragma unroll
                for (int i = 0; i < 5; i++) {
                    int fi = tid + i * BLKT;
                    if (fi < 2560) {
                        int row = fi / 20, p = fi % 20;
                        pfx[i] = *(const float2*)(
                            x + ((size_t)(b0 + row) * T_SEQ + (t + 1)) * D_IN + 2 * p);
                    }
                }
            } else {
                const uint4* src = (const uint4*)(
                    g_scr16 + ((size_t)blk * T_SEQ + (t + 1)) * (ROWS * H_DIM));
#pragma unroll
                for (int i = 0; i < 2; i++) pfh[i] = src[tid + i * BLKT];
            }
        }

        // ---- single-term GEMM: acc = A @ W^T ----
        const uint32_t aAh = aAbuf[t & 1];
        float acc[64];
#pragma unroll
        for (int i = 0; i < 64; i++) acc[i] = 0.0f;
#pragma unroll
        for (int ks = 0; ks < 8; ks++) {
            if (PA && ks == 3) continue;       // cols 48..63 are zero pad
            const uint32_t kb = (uint32_t)ks * 32;   // 16 halfs = 32 B
            uint32_t ah[2][4];
            ldsm4(ah[0], aAh + kb);
            ldsm4(ah[1], aAh + 16 * AST * 2 + kb);
#pragma unroll
            for (int g4 = 0; g4 < 4; g4++) {
                uint32_t bh[4];
                ldsm4(bh, aBh + (uint32_t)g4 * 64 * AST * 2 + kb);
#pragma unroll
                for (int mt = 0; mt < 2; mt++) {
                    float* a0 = &acc[((g4 * 2 + 0) * 2 + mt) * 4];
                    float* a1 = &acc[((g4 * 2 + 1) * 2 + mt) * 4];
                    mma16816(a0, ah[mt], bh[0], bh[1]);
                    mma16816(a1, ah[mt], bh[2], bh[3]);
                }
            }
        }

        // ---- epilogue: gates -> c, h_t -> write buffer ----
        unsigned char* bufW = sm + ((t & 1) ? SM_A0H : SM_A1H);
        const bool last = (!PA) && (t == T_SEQ - 1);
        __half* gscr = PA ?
            g_scr16 + ((size_t)blk * T_SEQ + t) * (ROWS * H_DIM) : nullptr;
#pragma unroll
        for (int mt = 0; mt < 2; mt++)
#pragma unroll
        for (int rr = 0; rr < 2; rr++)
#pragma unroll
        for (int nt = 0; nt < 2; nt++) {
            const int jj = j0 + nt * 8 + 2 * tig;
            float2 bi = *(const float2*)(sBias + jj);
            float2 bf = *(const float2*)(sBias + 64 + jj);
            float2 bg = *(const float2*)(sBias + 128 + jj);
            float2 bo = *(const float2*)(sBias + 192 + jj);
            float hv[2];
#pragma unroll
            for (int e = 0; e < 2; e++) {
                float pi = acc[((0 * 2 + nt) * 2 + mt) * 4 + rr * 2 + e] + (e ? bi.y : bi.x);
                float pf = acc[((1 * 2 + nt) * 2 + mt) * 4 + rr * 2 + e] + (e ? bf.y : bf.x);
                float pg = acc[((2 * 2 + nt) * 2 + mt) * 4 + rr * 2 + e] + (e ? bg.y : bg.x);
                float po = acc[((3 * 2 + nt) * 2 + mt) * 4 + rr * 2 + e] + (e ? bo.y : bo.x);
                float ig = sig_ap(pi), fg = sig_ap(pf);
                float gg = tanh_ap(pg), og = sig_ap(po);
                int ci = ((mt * 2 + rr) * 2 + nt) * 2 + e;
                float cn = fmaf(fg, c[ci], ig * gg);
                c[ci] = cn;
                hv[e] = og * tanh_ap(cn);
            }
            const int row = m0 + mt * 16 + rr * 8 + g8;
            if (last) {
                *(float2*)((float*)(sm + SM_A1H) + row * 64 + jj) =
                    make_float2(hv[0], hv[1]);
            } else {
                __half2 hp = __halves2half2(__float2half_rn(hv[0]),
                                            __float2half_rn(hv[1]));
                uint32_t off = (uint32_t)((row * AST + 64 + jj) * 2);
                *(__half2*)(bufW + off) = hp;
                if (PA)
                    *(__half2*)(gscr + row * 64 + jj) = hp;
            }
        }

        // ---- store prefetched t+1 staging into the write buffer ----
        if (t + 1 < T_SEQ) {
            if (PA) {
#pragma unroll
                for (int i = 0; i < 5; i++) {
                    int fi = tid + i * BLKT;
                    if (fi < 2560) {
                        int row = fi / 20, p = fi % 20;
                        *(__half2*)(bufW + (uint32_t)((row * AST + 2 * p) * 2)) =
                            __halves2half2(__float2half_rn(pfx[i].x),
                                           __float2half_rn(pfx[i].y));
                    }
                }
            } else {
#pragma unroll
                for (int i = 0; i < 2; i++) {
                    int fi = tid + i * BLKT;
                    int row = fi >> 3, seg = fi & 7;
                    *(uint4*)(bufW + (uint32_t)(row * (AST * 2) + seg * 16)) = pfh[i];
                }
            }
        }
    }
}

__global__ void __launch_bounds__(BLKT, 1)
rainfall_lstm_hmma6_kernel(
    const float* __restrict__ x,
    const float* __restrict__ Wih0, const float* __restrict__ Whh0,
    const float* __restrict__ bih0, const float* __restrict__ bhh0,
    const float* __restrict__ Wih1, const float* __restrict__ Whh1,
    const float* __restrict__ bih1, const float* __restrict__ bhh1,
    const float* __restrict__ W1, const float* __restrict__ b1,
    const float* __restrict__ W2, const float* __restrict__ b2,
    float* __restrict__ out)
{
    extern __shared__ unsigned char sm[];
    const uint32_t smb = smem_u32(sm);
    const int tid = threadIdx.x;
    const int blk = blockIdx.x;
    const int b0 = blk * ROWS;

    // ---- phase A setup ----
    stage_weights(Wih0, D_IN, Whh0, bih0, bhh0, sm, tid);
    {   // zero both A buffers (x pad cols 40..63 stay 0 forever; h0 = 0)
        uint4 z = make_uint4(0, 0, 0, 0);
        uint4* za = (uint4*)(sm + SM_A0H);
        for (int i = tid; i < (2 * 34816) / 16; i += BLKT) za[i] = z;
    }
    __syncthreads();
    run_phase<true>(sm, smb, x, b0, blk, tid);
    __syncthreads();   // phase-A writes done before W restage

    // ---- phase B setup ----
    stage_weights(Wih1, H_DIM, Whh1, bih1, bhh1, sm, tid);
    {   // zero both A buffers (h0 = 0 for layer 1)
        uint4 z = make_uint4(0, 0, 0, 0);
        uint4* za = (uint4*)(sm + SM_A0H);
        for (int i = tid; i < (2 * 34816) / 16; i += BLKT) za[i] = z;
    }
    {   // FC weights
        float* fw = (float*)(sm + SM_FC);
        for (int i = tid; i < FC_DIM * H_DIM; i += BLKT) fw[i] = W1[i];
        if (tid < FC_DIM) { fw[2048 + tid] = b1[tid]; fw[2080 + tid] = W2[tid]; }
        if (tid == 0) fw[2112] = b2[0];
    }
    __syncthreads();
    run_phase<false>(sm, smb, nullptr, b0, blk, tid);
    __syncthreads();   // final fp32 h2 (in SM_A1H) complete

    // ---- FC head: one thread per row ----
    if (tid < ROWS) {
        const float* sFC = (const float*)(sm + SM_A1H);
        const float* fw = (const float*)(sm + SM_FC);
        float hv[H_DIM];
#pragma unroll
        for (int j = 0; j < H_DIM; j++) hv[j] = sFC[tid * 64 + j];
        float o = fw[2112];
#pragma unroll
        for (int r = 0; r < FC_DIM; r++) {
            float a = fw[2048 + r];
            const float* wr = fw + r * H_DIM;
#pragma unroll
            for (int j = 0; j < H_DIM; j++) a = fmaf(hv[j], wr[j], a);
            o = fmaf(fmaxf(a, 0.0f), fw[2080 + r], o);
        }
        out[b0 + tid] = o;
    }
}

extern "C" void kernel_launch(void* const* d_in, const int* in_sizes, int n_in,
                              void* d_out, int out_size)
{
    (void)in_sizes; (void)n_in; (void)out_size;
    const float* x    = (const float*)d_in[0];
    const float* Wih0 = (const float*)d_in[1];
    const float* Whh0 = (const float*)d_in[2];
    const float* bih0 = (const float*)d_in[3];
    const float* bhh0 = (const float*)d_in[4];
    const float* Wih1 = (const float*)d_in[5];
    const float* Whh1 = (const float*)d_in[6];
    const float* bih1 = (const float*)d_in[7];
    const float* bhh1 = (const float*)d_in[8];
    const float* W1   = (const float*)d_in[9];
    const float* b1   = (const float*)d_in[10];
    const float* W2   = (const float*)d_in[11];
    const float* b2   = (const float*)d_in[12];
    float* out = (float*)d_out;

    cudaFuncSetAttribute(rainfall_lstm_hmma6_kernel,
                         cudaFuncAttributeMaxDynamicSharedMemorySize,
                         SM_TOTAL);

    rainfall_lstm_hmma6_kernel<<<NBLK, BLKT, SM_TOTAL>>>(
        x, Wih0, Whh0, bih0, bhh0, Wih1, Whh1, bih1, bhh1,
        W1, b1, W2, b2, out);
}

// round 15
// speedup vs baseline: 2.2196x; 1.0469x over previous
#include <cuda_runtime.h>
#include <cuda_fp16.h>
#include <cstddef>
#include <cstdint>

#define B_TOTAL 32768
#define T_SEQ   7
#define D_IN    40
#define H_DIM   64
#define FC_DIM  32
#define ROWS    128                // batch rows per block (2 groups x 64)
#define GROWS   64
#define BLKT    512
#define GTHR    256                // threads per group
#define NBLK    (B_TOTAL / ROWS)   // 256
#define AST     136                // padded stride in halfs (272 B)
#define GRPB    (GROWS * AST * 2)  // 17408 B: one A buffer for one group

// ---------------- smem byte offsets ----------------
#define SM_A0H  0                       // A buf0: [group0 | group1], GRPB each
#define SM_A1H  34816                   // A buf1: [group0 | group1]
#define SM_BH   69632                   // W fp16 [256][AST] halfs (shared)
#define SM_BIAS 139264                  // 256 fp32
#define SM_FC   140288                  // FC weights fp32
#define SM_TOTAL 148740

// phase-A hidden states, fp16: [blk][t][128][64]
__device__ __align__(16) __half g_scr16[(size_t)NBLK * T_SEQ * ROWS * H_DIM];

// ---------------- helpers ----------------
__device__ __forceinline__ uint32_t smem_u32(const void* p) {
    uint32_t a;
    asm("{ .reg .u64 t; cvta.to.shared.u64 t, %1; cvt.u32.u64 %0, t; }" : "=r"(a) : "l"(p));
    return a;
}
__device__ __forceinline__ void ldsm4(uint32_t r[4], uint32_t addr) {
    asm volatile("ldmatrix.sync.aligned.m8n8.x4.shared.b16 {%0,%1,%2,%3}, [%4];"
        : "=r"(r[0]), "=r"(r[1]), "=r"(r[2]), "=r"(r[3]) : "r"(addr));
}
__device__ __forceinline__ void mma16816(float* c, const uint32_t a[4],
                                         uint32_t b0, uint32_t b1) {
    asm volatile(
        "mma.sync.aligned.m16n8k16.row.col.f32.f16.f16.f32 "
        "{%0,%1,%2,%3}, {%4,%5,%6,%7}, {%8,%9}, {%0,%1,%2,%3};"
        : "+f"(c[0]), "+f"(c[1]), "+f"(c[2]), "+f"(c[3])
        : "r"(a[0]), "r"(a[1]), "r"(a[2]), "r"(a[3]), "r"(b0), "r"(b1));
}
__device__ __forceinline__ void gbar(int group) {
    asm volatile("bar.sync %0, %1;" :: "r"(group + 1), "r"(GTHR) : "memory");
}
__device__ __forceinline__ float tanh_ap(float x) {
    float y; asm("tanh.approx.f32 %0, %1;" : "=f"(y) : "f"(x)); return y;
}
__device__ __forceinline__ float sig_ap(float x) {
    return fmaf(0.5f, tanh_ap(0.5f * x), 0.5f);
}

// ---------------- weight staging: fp32 -> fp16 [256][AST] ----------------
// cols [0,Kx) = W_in, cols [64,128) = W_hh (combined A-tile K layout)
__device__ void stage_weights(const float* __restrict__ Wx, int Kx,
                              const float* __restrict__ Wh,
                              const float* __restrict__ bi, const float* __restrict__ bh,
                              unsigned char* sm, int tid)
{
    uint4 z = make_uint4(0, 0, 0, 0);
    uint4* zb = (uint4*)(sm + SM_BH);
    for (int i = tid; i < 69632 / 16; i += BLKT) zb[i] = z;
    __syncthreads();

    for (int e = tid; e < 256 * Kx; e += BLKT) {
        int c = e / Kx, k = e % Kx;
        *(__half*)(sm + SM_BH + (uint32_t)(c * AST + k) * 2) = __float2half_rn(Wx[e]);
    }
    for (int e = tid; e < 256 * H_DIM; e += BLKT) {
        int c = e / H_DIM, k = e % H_DIM;
        *(__half*)(sm + SM_BH + (uint32_t)(c * AST + 64 + k) * 2) = __float2half_rn(Wh[e]);
    }
    float* sB = (float*)(sm + SM_BIAS);
    for (int i = tid; i < 256; i += BLKT) sB[i] = bi[i] + bh[i];
}

// ------ one LSTM layer (7 steps), per-group named barriers, prefetched staging
template <bool PA>
__device__ void run_phase(unsigned char* sm, uint32_t smb,
                          const float* __restrict__ x, int b0, int blk, int tid)
{
    const int group = tid >> 8, gtid = tid & 255;
    const int wg = gtid >> 5, lane = gtid & 31;
    const int m0 = (wg >> 2) * 32, j0 = (wg & 3) * 16;   // local rows 0..63
    const int tig = lane & 3, g8 = lane >> 2;
    const int part = lane >> 3, l = lane & 7;
    const int grow0 = group * GROWS;                      // block-row base

    const uint32_t aoff =
        (uint32_t)(((m0 + (part & 1) * 8 + l) * AST + (part >> 1) * 8) * 2);
    const uint32_t boff =
        (uint32_t)(((j0 + (part >> 1) * 8 + l) * AST + (part & 1) * 8) * 2);
    const uint32_t aBh = smb + SM_BH + boff;
    const uint32_t aAbuf[2] = { smb + SM_A0H + (uint32_t)group * GRPB + aoff,
                                smb + SM_A1H + (uint32_t)group * GRPB + aoff };
    const float* sBias = (const float*)(sm + SM_BIAS);

    float c[16];
#pragma unroll
    for (int i = 0; i < 16; i++) c[i] = 0.0f;

    // ---- pre-stage t=0 into this group's buf0 ----
    unsigned char* buf0 = sm + SM_A0H + group * GRPB;
    if (PA) {
#pragma unroll
        for (int i = 0; i < 5; i++) {
            int fi = gtid + i * GTHR;           // 0..1279 float2 of x_0 (64 rows)
            int row = fi / 20, p = fi % 20;
            float2 v = *(const float2*)(
                x + ((size_t)(b0 + grow0 + row) * T_SEQ + 0) * D_IN + 2 * p);
            *(__half2*)(buf0 + (uint32_t)((row * AST + 2 * p) * 2)) =
                __halves2half2(__float2half_rn(v.x), __float2half_rn(v.y));
        }
    } else {
        const uint4* src = (const uint4*)(g_scr16 +
            ((size_t)blk * T_SEQ * ROWS + grow0) * H_DIM);
#pragma unroll
        for (int i = 0; i < 2; i++) {
            int fi = gtid + i * GTHR;           // 0..511 uint4 (8 halfs each)
            int row = fi >> 3, seg = fi & 7;
            *(uint4*)(buf0 + (uint32_t)(row * (AST * 2) + seg * 16)) = src[fi];
        }
    }

    for (int t = 0; t < T_SEQ; t++) {
        gbar(group);   // group's read buffer (x_t staged + h_{t-1}) ready

        // ---- prefetch t+1 staging loads (latency off critical path) ----
        float2 pfx[5];
        uint4  pfh[2];
        if (t + 1 < T_SEQ) {
            if (PA) {
#pragma unroll
                for (int i = 0; i < 5; i++) {
                    int fi = gtid + i * GTHR;
                    int row = fi / 20, p = fi % 20;
                    pfx[i] = *(const float2*)(
                        x + ((size_t)(b0 + grow0 + row) * T_SEQ + (t + 1)) * D_IN + 2 * p);
                }
            } else {
                const uint4* src = (const uint4*)(g_scr16 +
                    (((size_t)blk * T_SEQ + (t + 1)) * ROWS + grow0) * H_DIM);
#pragma unroll
                for (int i = 0; i < 2; i++) pfh[i] = src[gtid + i * GTHR];
            }
        }

        // ---- single-term GEMM: acc = A @ W^T ----
        const uint32_t aAh = aAbuf[t & 1];
        float acc[64];
#pragma unroll
        for (int i = 0; i < 64; i++) acc[i] = 0.0f;
#pragma unroll
        for (int ks = 0; ks < 8; ks++) {
            if (PA && ks == 3) continue;       // cols 48..63 are zero pad
            const uint32_t kb = (uint32_t)ks * 32;   // 16 halfs = 32 B
            uint32_t ah[2][4];
            ldsm4(ah[0], aAh + kb);
            ldsm4(ah[1], aAh + 16 * AST * 2 + kb);
#pragma unroll
            for (int g4 = 0; g4 < 4; g4++) {
                uint32_t bh[4];
                ldsm4(bh, aBh + (uint32_t)g4 * 64 * AST * 2 + kb);
#pragma unroll
                for (int mt = 0; mt < 2; mt++) {
                    float* a0 = &acc[((g4 * 2 + 0) * 2 + mt) * 4];
                    float* a1 = &acc[((g4 * 2 + 1) * 2 + mt) * 4];
                    mma16816(a0, ah[mt], bh[0], bh[1]);
                    mma16816(a1, ah[mt], bh[2], bh[3]);
                }
            }
        }

        // ---- epilogue: gates -> c, h_t -> group's write buffer ----
        unsigned char* bufW = sm + ((t & 1) ? SM_A0H : SM_A1H) + group * GRPB;
        const bool last = (!PA) && (t == T_SEQ - 1);
        __half* gscr = PA ?
            g_scr16 + (((size_t)blk * T_SEQ + t) * ROWS + grow0) * H_DIM : nullptr;
#pragma unroll
        for (int mt = 0; mt < 2; mt++)
#pragma unroll
        for (int rr = 0; rr < 2; rr++)
#pragma unroll
        for (int nt = 0; nt < 2; nt++) {
            const int jj = j0 + nt * 8 + 2 * tig;
            float2 bi = *(const float2*)(sBias + jj);
            float2 bf = *(const float2*)(sBias + 64 + jj);
            float2 bg = *(const float2*)(sBias + 128 + jj);
            float2 bo = *(const float2*)(sBias + 192 + jj);
            float hv[2];
#pragma unroll
            for (int e = 0; e < 2; e++) {
                float pi = acc[((0 * 2 + nt) * 2 + mt) * 4 + rr * 2 + e] + (e ? bi.y : bi.x);
                float pf = acc[((1 * 2 + nt) * 2 + mt) * 4 + rr * 2 + e] + (e ? bf.y : bf.x);
                float pg = acc[((2 * 2 + nt) * 2 + mt) * 4 + rr * 2 + e] + (e ? bg.y : bg.x);
                float po = acc[((3 * 2 + nt) * 2 + mt) * 4 + rr * 2 + e] + (e ? bo.y : bo.x);
                float ig = sig_ap(pi), fg = sig_ap(pf);
                float gg = tanh_ap(pg), og = sig_ap(po);
                int ci = ((mt * 2 + rr) * 2 + nt) * 2 + e;
                float cn = fmaf(fg, c[ci], ig * gg);
                c[ci] = cn;
                hv[e] = og * tanh_ap(cn);
            }
            const int row = m0 + mt * 16 + rr * 8 + g8;   // local 0..63
            if (last) {
                // fp32 h2 into this group's buf1 region: [64][64] fp32 = 16 KB
                *(float2*)((float*)(sm + SM_A1H + group * GRPB) + row * 64 + jj) =
                    make_float2(hv[0], hv[1]);
            } else {
                __half2 hp = __halves2half2(__float2half_rn(hv[0]),
                                            __float2half_rn(hv[1]));
                uint32_t off = (uint32_t)((row * AST + 64 + jj) * 2);
                *(__half2*)(bufW + off) = hp;
                if (PA)
                    *(__half2*)(gscr + row * 64 + jj) = hp;
            }
        }

        // ---- store prefetched t+1 staging into the write buffer ----
        if (t + 1 < T_SEQ) {
            if (PA) {
#pragma unroll
                for (int i = 0; i < 5; i++) {
                    int fi = gtid + i * GTHR;
                    int row = fi / 20, p = fi % 20;
                    *(__half2*)(bufW + (uint32_t)((row * AST + 2 * p) * 2)) =
                        __halves2half2(__float2half_rn(pfx[i].x),
                                       __float2half_rn(pfx[i].y));
                }
            } else {
#pragma unroll
                for (int i = 0; i < 2; i++) {
                    int fi = gtid + i * GTHR;
                    int row = fi >> 3, seg = fi & 7;
                    *(uint4*)(bufW + (uint32_t)(row * (AST * 2) + seg * 16)) = pfh[i];
                }
            }
        }
    }
}

__global__ void __launch_bounds__(BLKT, 1)
rainfall_lstm_hmma7_kernel(
    const float* __restrict__ x,
    const float* __restrict__ Wih0, const float* __restrict__ Whh0,
    const float* __restrict__ bih0, const float* __restrict__ bhh0,
    const float* __restrict__ Wih1, const float* __restrict__ Whh1,
    const float* __restrict__ bih1, const float* __restrict__ bhh1,
    const float* __restrict__ W1, const float* __restrict__ b1,
    const float* __restrict__ W2, const float* __restrict__ b2,
    float* __restrict__ out)
{
    extern __shared__ unsigned char sm[];
    const uint32_t smb = smem_u32(sm);
    const int tid = threadIdx.x;
    const int blk = blockIdx.x;
    const int b0 = blk * ROWS;

    // ---- phase A setup ----
    stage_weights(Wih0, D_IN, Whh0, bih0, bhh0, sm, tid);
    {   // zero both A buffers, both groups (x pad cols stay 0; h0 = 0)
        uint4 z = make_uint4(0, 0, 0, 0);
        uint4* za = (uint4*)(sm + SM_A0H);
        for (int i = tid; i < (2 * 34816) / 16; i += BLKT) za[i] = z;
    }
    __syncthreads();
    run_phase<true>(sm, smb, x, b0, blk, tid);
    __syncthreads();   // both groups done before W restage

    // ---- phase B setup ----
    stage_weights(Wih1, H_DIM, Whh1, bih1, bhh1, sm, tid);
    {   // zero both A buffers (h0 = 0 for layer 1)
        uint4 z = make_uint4(0, 0, 0, 0);
        uint4* za = (uint4*)(sm + SM_A0H);
        for (int i = tid; i < (2 * 34816) / 16; i += BLKT) za[i] = z;
    }
    {   // FC weights
        float* fw = (float*)(sm + SM_FC);
        for (int i = tid; i < FC_DIM * H_DIM; i += BLKT) fw[i] = W1[i];
        if (tid < FC_DIM) { fw[2048 + tid] = b1[tid]; fw[2080 + tid] = W2[tid]; }
        if (tid == 0) fw[2112] = b2[0];
    }
    __syncthreads();
    run_phase<false>(sm, smb, nullptr, b0, blk, tid);
    __syncthreads();   // both groups' fp32 h2 complete

    // ---- FC head: one thread per row ----
    if (tid < ROWS) {
        const int g = tid >> 6, lr = tid & 63;
        const float* sFC = (const float*)(sm + SM_A1H + g * GRPB);
        const float* fw = (const float*)(sm + SM_FC);
        float hv[H_DIM];
#pragma unroll
        for (int j = 0; j < H_DIM; j++) hv[j] = sFC[lr * 64 + j];
        float o = fw[2112];
#pragma unroll
        for (int r = 0; r < FC_DIM; r++) {
            float a = fw[2048 + r];
            const float* wr = fw + r * H_DIM;
#pragma unroll
            for (int j = 0; j < H_DIM; j++) a = fmaf(hv[j], wr[j], a);
            o = fmaf(fmaxf(a, 0.0f), fw[2080 + r], o);
        }
        out[b0 + tid] = o;
    }
}

extern "C" void kernel_launch(void* const* d_in, const int* in_sizes, int n_in,
                              void* d_out, int out_size)
{
    (void)in_sizes; (void)n_in; (void)out_size;
    const float* x    = (const float*)d_in[0];
    const float* Wih0 = (const float*)d_in[1];
    const float* Whh0 = (const float*)d_in[2];
    const float* bih0 = (const float*)d_in[3];
    const float* bhh0 = (const float*)d_in[4];
    const float* Wih1 = (const float*)d_in[5];
    const float* Whh1 = (const float*)d_in[6];
    const float* bih1 = (const float*)d_in[7];
    const float* bhh1 = (const float*)d_in[8];
    const float* W1   = (const float*)d_in[9];
    const float* b1   = (const float*)d_in[10];
    const float* W2   = (const float*)d_in[11];
    const float* b2   = (const float*)d_in[12];
    float* out = (float*)d_out;

    cudaFuncSetAttribute(rainfall_lstm_hmma7_kernel,
                         cudaFuncAttributeMaxDynamicSharedMemorySize,
                         SM_TOTAL);

    rainfall_lstm_hmma7_kernel<<<NBLK, BLKT, SM_TOTAL>>>(
        x, Wih0, Whh0, bih0, bhh0, Wih1, Whh1, bih1, bhh1,
        W1, b1, W2, b2, out);
}

// round 16
// speedup vs baseline: 2.2682x; 1.0219x over previous
#include <cuda_runtime.h>
#include <cuda_fp16.h>
#include <cstddef>
#include <cstdint>

#define B_TOTAL 32768
#define T_SEQ   7
#define D_IN    40
#define H_DIM   64
#define FC_DIM  32
#define ROWS    64                 // batch rows per block
#define BLKT    256                // 8 warps
#define NBLK    (B_TOTAL / ROWS)   // 512
#define AST     136                // padded stride in halfs (272 B)
#define ABUF    (ROWS * AST * 2)   // 17408 B per A buffer

// ---------------- smem byte offsets (total ~105.5 KB -> 2 CTAs/SM) ----------
#define SM_A0   0                       // A buf0 [64][AST] halfs; FC wts alias
#define SM_A1   17408                   // A buf1; final fp32 h2 alias
#define SM_BH   34816                   // W fp16 [256][AST] halfs
#define SM_BIAS 104448                  // 256 fp32
#define SM_TOTAL 105472
#define SM_FC   SM_A0                   // FC params live in A0 after recurrence

// phase-A hidden states, fp16: [blk][t][64][64]
__device__ __align__(16) __half g_scr16[(size_t)NBLK * T_SEQ * ROWS * H_DIM];

// ---------------- helpers ----------------
__device__ __forceinline__ uint32_t smem_u32(const void* p) {
    uint32_t a;
    asm("{ .reg .u64 t; cvta.to.shared.u64 t, %1; cvt.u32.u64 %0, t; }" : "=r"(a) : "l"(p));
    return a;
}
__device__ __forceinline__ void ldsm4(uint32_t r[4], uint32_t addr) {
    asm volatile("ldmatrix.sync.aligned.m8n8.x4.shared.b16 {%0,%1,%2,%3}, [%4];"
        : "=r"(r[0]), "=r"(r[1]), "=r"(r[2]), "=r"(r[3]) : "r"(addr));
}
__device__ __forceinline__ void mma16816(float* c, const uint32_t a[4],
                                         uint32_t b0, uint32_t b1) {
    asm volatile(
        "mma.sync.aligned.m16n8k16.row.col.f32.f16.f16.f32 "
        "{%0,%1,%2,%3}, {%4,%5,%6,%7}, {%8,%9}, {%0,%1,%2,%3};"
        : "+f"(c[0]), "+f"(c[1]), "+f"(c[2]), "+f"(c[3])
        : "r"(a[0]), "r"(a[1]), "r"(a[2]), "r"(a[3]), "r"(b0), "r"(b1));
}
__device__ __forceinline__ float tanh_ap(float x) {
    float y; asm("tanh.approx.f32 %0, %1;" : "=f"(y) : "f"(x)); return y;
}
__device__ __forceinline__ float sig_ap(float x) {
    return fmaf(0.5f, tanh_ap(0.5f * x), 0.5f);
}

// ---------------- weight staging: fp32 -> fp16 [256][AST] ----------------
// cols [0,Kx) = W_in, cols [64,128) = W_hh (combined A-tile K layout)
__device__ void stage_weights(const float* __restrict__ Wx, int Kx,
                              const float* __restrict__ Wh,
                              const float* __restrict__ bi, const float* __restrict__ bh,
                              unsigned char* sm, int tid)
{
    uint4 z = make_uint4(0, 0, 0, 0);
    uint4* zb = (uint4*)(sm + SM_BH);
    for (int i = tid; i < 69632 / 16; i += BLKT) zb[i] = z;
    __syncthreads();

    for (int e = tid; e < 256 * Kx; e += BLKT) {
        int c = e / Kx, k = e % Kx;
        *(__half*)(sm + SM_BH + (uint32_t)(c * AST + k) * 2) = __float2half_rn(Wx[e]);
    }
    for (int e = tid; e < 256 * H_DIM; e += BLKT) {
        int c = e / H_DIM, k = e % H_DIM;
        *(__half*)(sm + SM_BH + (uint32_t)(c * AST + 64 + k) * 2) = __float2half_rn(Wh[e]);
    }
    float* sB = (float*)(sm + SM_BIAS);
    for (int i = tid; i < 256; i += BLKT) sB[i] = bi[i] + bh[i];
}

// ---- one LSTM layer (7 steps), 1 sync/step, prefetched staging, 64 rows ----
template <bool PA>
__device__ void run_phase(unsigned char* sm, uint32_t smb,
                          const float* __restrict__ x, int b0, int blk, int tid)
{
    const int wg = tid >> 5, lane = tid & 31;
    const int m0 = (wg >> 2) * 32, j0 = (wg & 3) * 16;
    const int tig = lane & 3, g8 = lane >> 2;
    const int part = lane >> 3, l = lane & 7;

    const uint32_t aoff =
        (uint32_t)(((m0 + (part & 1) * 8 + l) * AST + (part >> 1) * 8) * 2);
    const uint32_t boff =
        (uint32_t)(((j0 + (part >> 1) * 8 + l) * AST + (part & 1) * 8) * 2);
    const uint32_t aBh = smb + SM_BH + boff;
    const uint32_t aAbuf[2] = { smb + SM_A0 + aoff, smb + SM_A1 + aoff };
    const float* sBias = (const float*)(sm + SM_BIAS);

    float c[16];
#pragma unroll
    for (int i = 0; i < 16; i++) c[i] = 0.0f;

    // ---- pre-stage t=0 into buf0 ----
    if (PA) {
#pragma unroll
        for (int i = 0; i < 5; i++) {
            int fi = tid + i * BLKT;            // 0..1279 float2 of x_0 (64 rows)
            int row = fi / 20, p = fi % 20;
            float2 v = *(const float2*)(
                x + ((size_t)(b0 + row) * T_SEQ + 0) * D_IN + 2 * p);
            *(__half2*)(sm + SM_A0 + (uint32_t)((row * AST + 2 * p) * 2)) =
                __halves2half2(__float2half_rn(v.x), __float2half_rn(v.y));
        }
    } else {
        const uint4* src = (const uint4*)(g_scr16 + (size_t)blk * T_SEQ * (ROWS * H_DIM));
#pragma unroll
        for (int i = 0; i < 2; i++) {
            int fi = tid + i * BLKT;            // 0..511 uint4 (8 halfs each)
            int row = fi >> 3, seg = fi & 7;
            *(uint4*)(sm + SM_A0 + (uint32_t)(row * (AST * 2) + seg * 16)) = src[fi];
        }
    }

    for (int t = 0; t < T_SEQ; t++) {
        __syncthreads();   // read buffer (x_t staged + h_{t-1} from epi) ready

        // ---- prefetch t+1 staging loads (latency off critical path) ----
        float2 pfx[5];
        uint4  pfh[2];
        if (t + 1 < T_SEQ) {
            if (PA) {
#pragma unroll
                for (int i = 0; i < 5; i++) {
                    int fi = tid + i * BLKT;
                    int row = fi / 20, p = fi % 20;
                    pfx[i] = *(const float2*)(
                        x + ((size_t)(b0 + row) * T_SEQ + (t + 1)) * D_IN + 2 * p);
                }
            } else {
                const uint4* src = (const uint4*)(
                    g_scr16 + ((size_t)blk * T_SEQ + (t + 1)) * (ROWS * H_DIM));
#pragma unroll
                for (int i = 0; i < 2; i++) pfh[i] = src[tid + i * BLKT];
            }
        }

        // ---- single-term GEMM: acc = A @ W^T ----
        const uint32_t aAh = aAbuf[t & 1];
        float acc[64];
#pragma unroll
        for (int i = 0; i < 64; i++) acc[i] = 0.0f;
#pragma unroll
        for (int ks = 0; ks < 8; ks++) {
            if (PA && ks == 3) continue;       // cols 48..63 are zero pad
            const uint32_t kb = (uint32_t)ks * 32;   // 16 halfs = 32 B
            uint32_t ah[2][4];
            ldsm4(ah[0], aAh + kb);
            ldsm4(ah[1], aAh + 16 * AST * 2 + kb);
#pragma unroll
            for (int g4 = 0; g4 < 4; g4++) {
                uint32_t bh[4];
                ldsm4(bh, aBh + (uint32_t)g4 * 64 * AST * 2 + kb);
#pragma unroll
                for (int mt = 0; mt < 2; mt++) {
                    float* a0 = &acc[((g4 * 2 + 0) * 2 + mt) * 4];
                    float* a1 = &acc[((g4 * 2 + 1) * 2 + mt) * 4];
                    mma16816(a0, ah[mt], bh[0], bh[1]);
                    mma16816(a1, ah[mt], bh[2], bh[3]);
                }
            }
        }

        // ---- epilogue: gates -> c, h_t -> write buffer ----
        unsigned char* bufW = sm + ((t & 1) ? SM_A0 : SM_A1);
        const bool last = (!PA) && (t == T_SEQ - 1);
        __half* gscr = PA ?
            g_scr16 + ((size_t)blk * T_SEQ + t) * (ROWS * H_DIM) : nullptr;
#pragma unroll
        for (int mt = 0; mt < 2; mt++)
#pragma unroll
        for (int rr = 0; rr < 2; rr++)
#pragma unroll
        for (int nt = 0; nt < 2; nt++) {
            const int jj = j0 + nt * 8 + 2 * tig;
            float2 bi = *(const float2*)(sBias + jj);
            float2 bf = *(const float2*)(sBias + 64 + jj);
            float2 bg = *(const float2*)(sBias + 128 + jj);
            float2 bo = *(const float2*)(sBias + 192 + jj);
            float hv[2];
#pragma unroll
            for (int e = 0; e < 2; e++) {
                float pi = acc[((0 * 2 + nt) * 2 + mt) * 4 + rr * 2 + e] + (e ? bi.y : bi.x);
                float pf = acc[((1 * 2 + nt) * 2 + mt) * 4 + rr * 2 + e] + (e ? bf.y : bf.x);
                float pg = acc[((2 * 2 + nt) * 2 + mt) * 4 + rr * 2 + e] + (e ? bg.y : bg.x);
                float po = acc[((3 * 2 + nt) * 2 + mt) * 4 + rr * 2 + e] + (e ? bo.y : bo.x);
                float ig = sig_ap(pi), fg = sig_ap(pf);
                float gg = tanh_ap(pg), og = sig_ap(po);
                int ci = ((mt * 2 + rr) * 2 + nt) * 2 + e;
                float cn = fmaf(fg, c[ci], ig * gg);
                c[ci] = cn;
                hv[e] = og * tanh_ap(cn);
            }
            const int row = m0 + mt * 16 + rr * 8 + g8;   // 0..63
            if (last) {
                // fp32 h2 into A1 region: [64][64] fp32 = 16 KB
                *(float2*)((float*)(sm + SM_A1) + row * 64 + jj) =
                    make_float2(hv[0], hv[1]);
            } else {
                __half2 hp = __halves2half2(__float2half_rn(hv[0]),
                                            __float2half_rn(hv[1]));
                uint32_t off = (uint32_t)((row * AST + 64 + jj) * 2);
                *(__half2*)(bufW + off) = hp;
                if (PA)
                    *(__half2*)(gscr + row * 64 + jj) = hp;
            }
        }

        // ---- store prefetched t+1 staging into the write buffer ----
        if (t + 1 < T_SEQ) {
            if (PA) {
#pragma unroll
                for (int i = 0; i < 5; i++) {
                    int fi = tid + i * BLKT;
                    int row = fi / 20, p = fi % 20;
                    *(__half2*)(bufW + (uint32_t)((row * AST + 2 * p) * 2)) =
                        __halves2half2(__float2half_rn(pfx[i].x),
                                       __float2half_rn(pfx[i].y));
                }
            } else {
#pragma unroll
                for (int i = 0; i < 2; i++) {
                    int fi = tid + i * BLKT;
                    int row = fi >> 3, seg = fi & 7;
                    *(uint4*)(bufW + (uint32_t)(row * (AST * 2) + seg * 16)) = pfh[i];
                }
            }
        }
    }
}

__global__ void __launch_bounds__(BLKT, 2)
rainfall_lstm_hmma8_kernel(
    const float* __restrict__ x,
    const float* __restrict__ Wih0, const float* __restrict__ Whh0,
    const float* __restrict__ bih0, const float* __restrict__ bhh0,
    const float* __restrict__ Wih1, const float* __restrict__ Whh1,
    const float* __restrict__ bih1, const float* __restrict__ bhh1,
    const float* __restrict__ W1, const float* __restrict__ b1,
    const float* __restrict__ W2, const float* __restrict__ b2,
    float* __restrict__ out)
{
    extern __shared__ unsigned char sm[];
    const uint32_t smb = smem_u32(sm);
    const int tid = threadIdx.x;
    const int blk = blockIdx.x;
    const int b0 = blk * ROWS;

    // ---- phase A setup ----
    stage_weights(Wih0, D_IN, Whh0, bih0, bhh0, sm, tid);
    {   // zero both A buffers (x pad cols stay 0; h0 = 0)
        uint4 z = make_uint4(0, 0, 0, 0);
        uint4* za = (uint4*)(sm + SM_A0);
        for (int i = tid; i < (2 * ABUF) / 16; i += BLKT) za[i] = z;
    }
    __syncthreads();
    run_phase<true>(sm, smb, x, b0, blk, tid);
    __syncthreads();   // phase-A writes done before W restage

    // ---- phase B setup ----
    stage_weights(Wih1, H_DIM, Whh1, bih1, bhh1, sm, tid);
    {   // zero both A buffers (h0 = 0 for layer 1)
        uint4 z = make_uint4(0, 0, 0, 0);
        uint4* za = (uint4*)(sm + SM_A0);
        for (int i = tid; i < (2 * ABUF) / 16; i += BLKT) za[i] = z;
    }
    __syncthreads();
    run_phase<false>(sm, smb, nullptr, b0, blk, tid);
    __syncthreads();   // fp32 h2 (in A1) complete; A0 now free

    // ---- load FC params into A0 region ----
    {
        float* fw = (float*)(sm + SM_FC);
        for (int i = tid; i < FC_DIM * H_DIM; i += BLKT) fw[i] = W1[i];
        if (tid < FC_DIM) { fw[2048 + tid] = b1[tid]; fw[2080 + tid] = W2[tid]; }
        if (tid == 0) fw[2112] = b2[0];
    }
    __syncthreads();

    // ---- FC head: one thread per row ----
    if (tid < ROWS) {
        const float* sFC = (const float*)(sm + SM_A1);
        const float* fw = (const float*)(sm + SM_FC);
        float hv[H_DIM];
#pragma unroll
        for (int j = 0; j < H_DIM; j++) hv[j] = sFC[tid * 64 + j];
        float o = fw[2112];
#pragma unroll
        for (int r = 0; r < FC_DIM; r++) {
            float a = fw[2048 + r];
            const float* wr = fw + r * H_DIM;
#pragma unroll
            for (int j = 0; j < H_DIM; j++) a = fmaf(hv[j], wr[j], a);
            o = fmaf(fmaxf(a, 0.0f), fw[2080 + r], o);
        }
        out[b0 + tid] = o;
    }
}

extern "C" void kernel_launch(void* const* d_in, const int* in_sizes, int n_in,
                              void* d_out, int out_size)
{
    (void)in_sizes; (void)n_in; (void)out_size;
    const float* x    = (const float*)d_in[0];
    const float* Wih0 = (const float*)d_in[1];
    const float* Whh0 = (const float*)d_in[2];
    const float* bih0 = (const float*)d_in[3];
    const float* bhh0 = (const float*)d_in[4];
    const float* Wih1 = (const float*)d_in[5];
    const float* Whh1 = (const float*)d_in[6];
    const float* bih1 = (const float*)d_in[7];
    const float* bhh1 = (const float*)d_in[8];
    const float* W1   = (const float*)d_in[9];
    const float* b1   = (const float*)d_in[10];
    const float* W2   = (const float*)d_in[11];
    const float* b2   = (const float*)d_in[12];
    float* out = (float*)d_out;

    cudaFuncSetAttribute(rainfall_lstm_hmma8_kernel,
                         cudaFuncAttributeMaxDynamicSharedMemorySize,
                         SM_TOTAL);

    rainfall_lstm_hmma8_kernel<<<NBLK, BLKT, SM_TOTAL>>>(
        x, Wih0, Whh0, bih0, bhh0, Wih1, Whh1, bih1, bhh1,
        W1, b1, W2, b2, out);
}